// round 8
// baseline (speedup 1.0000x reference)
#include <cuda_runtime.h>

#define IN_DIM 768
#define OUT_DIM 768
#define BATCH 32
#define NUMF 8
#define NROWS 9                    // 8 sin rows + 1 silu row

#define CHUNK 8                    // i's per block
#define NSPLIT (IN_DIM / CHUNK)    // 96 k-splits
#define O_TILE 128
#define THREADS 128                // 4 warps = 4 batch-groups; lane = o
#define WSTRIDE 68                 // floats/row: 64 w + pad; 68%32==4 -> lanes tile all banks

typedef unsigned long long u64;

// Combined basis: g_S[(i*9 + r)*32 + b], r=0..7: sin((r+1)*x), r=8: silu(x)
__device__ float g_S[IN_DIM * NROWS * BATCH];
// Partials, layout [split][bpair(16)][o(768)] packed f32x2 -> coalesced stores & reduce
__device__ u64 g_part[NSPLIT * (BATCH / 2) * OUT_DIM];

// ---- f32x2 helpers ----
__device__ __forceinline__ u64 pk2(float v) {
    u64 r; asm("mov.b64 %0, {%1, %1};" : "=l"(r) : "f"(v)); return r;
}
__device__ __forceinline__ u64 pk2ab(float a, float b) {
    u64 r; asm("mov.b64 %0, {%1, %2};" : "=l"(r) : "f"(a), "f"(b)); return r;
}
__device__ __forceinline__ void upk2(u64 v, float& lo, float& hi) {
    asm("mov.b64 {%0, %1}, %2;" : "=f"(lo), "=f"(hi) : "l"(v));
}
__device__ __forceinline__ void fma2(u64& d, u64 a, u64 b) {
    asm("fma.rn.f32x2 %0, %1, %2, %0;" : "+l"(d) : "l"(a), "l"(b));
}
__device__ __forceinline__ u64 mul2(u64 a, u64 b) {
    u64 r; asm("mul.rn.f32x2 %0, %1, %2;" : "=l"(r) : "l"(a), "l"(b)); return r;
}
__device__ __forceinline__ void add2(u64& d, u64 a) {
    asm("add.rn.f32x2 %0, %0, %1;" : "+l"(d) : "l"(a));
}

// -------- Kernel P: basis precompute, coalesced via smem transpose --------
// 192 blocks x 128 thr; block handles 4 i x 32 b.
__global__ __launch_bounds__(128) void precompute_kernel(
    const float* __restrict__ x, const float* __restrict__ grid) {
    __shared__ float xs[4][33];
    int tid = threadIdx.x;
    int i0 = blockIdx.x * 4;

    // coalesced-ish load: per warp 8 b-rows x 16B segments (8 sectors vs 32 lines)
    {
        int b = tid >> 2;
        int iofs = tid & 3;
        xs[iofs][b] = x[b * IN_DIM + i0 + iofs];
    }
    __syncthreads();

    int ii = tid >> 5;
    int b = tid & 31;
    int i = i0 + ii;
    float xv = xs[ii][b];

    float theta = __ldg(grid) * xv;
    float s1 = __sinf(theta);
    float c2 = 2.0f * __cosf(theta);
    float sm1 = s1, sm2 = 0.0f;
    g_S[(i * NROWS + 0) * BATCH + b] = s1;
#pragma unroll
    for (int k = 1; k < NUMF; k++) {
        float sk = fmaf(c2, sm1, -sm2);
        sm2 = sm1; sm1 = sk;
        g_S[(i * NROWS + k) * BATCH + b] = sk;
    }
    g_S[(i * NROWS + 8) * BATCH + b] = xv / (1.0f + __expf(-xv));   // silu
}

// -------- Kernel G: skinny GEMM --------
// Warp = one batch-group (8 b); lane = o; thread tile 4 o (j*32+lane) x 8 b.
// s-row loads are warp-uniform -> smem broadcast.
__global__ __launch_bounds__(THREADS, 4) void gemm_kernel(
    const float* __restrict__ coef,
    const float* __restrict__ scale_sp,
    const float* __restrict__ scale_base) {

    __shared__ __align__(16) float stile[CHUNK * NROWS * BATCH];    // 9216 B
    __shared__ __align__(16) float wtile[O_TILE * WSTRIDE];         // 34816 B
    __shared__ float sbtile[O_TILE * 9];                            // 4608 B (stride 9)

    int tid = threadIdx.x;
    int lane = tid & 31;
    int bg = tid >> 5;            // warp id = batch-group
    int split = blockIdx.y;
    int i0 = split * CHUNK;
    int oBase = blockIdx.x * O_TILE;

    // ---- stage s basis: contiguous float4 copy (2304 floats) ----
    {
        const float4* src = reinterpret_cast<const float4*>(g_S) + i0 * (NROWS * BATCH / 4);
        float4* dst = reinterpret_cast<float4*>(stile);
#pragma unroll
        for (int f = tid; f < CHUNK * NROWS * BATCH / 4; f += THREADS)
            dst[f] = src[f];
    }

    // ---- stage w pre-scaled by scale_sp, packed f32x2 multiplies ----
    // granule = one (o,i) idx = 8 floats (2 LDG.128), one scale_sp load.
#pragma unroll
    for (int f = tid; f < O_TILE * CHUNK; f += THREADS) {   // 1024 granules
        int o_l = f >> 3;
        int i_l = f & 7;
        int idx = (oBase + o_l) * IN_DIM + i0 + i_l;
        float4 c0 = reinterpret_cast<const float4*>(coef)[idx * 2];
        float4 c1 = reinterpret_cast<const float4*>(coef)[idx * 2 + 1];
        u64 sp2 = pk2(__ldg(scale_sp + idx));
        u64 v0 = mul2(pk2ab(c0.x, c0.y), sp2);
        u64 v1 = mul2(pk2ab(c0.z, c0.w), sp2);
        u64 v2 = mul2(pk2ab(c1.x, c1.y), sp2);
        u64 v3 = mul2(pk2ab(c1.z, c1.w), sp2);
        u64* wp = reinterpret_cast<u64*>(wtile + o_l * WSTRIDE + i_l * 8);
        wp[0] = v0; wp[1] = v1; wp[2] = v2; wp[3] = v3;
    }
#pragma unroll
    for (int f = tid; f < O_TILE * CHUNK; f += THREADS) {
        int o_l = f >> 3;
        int ii = f & 7;
        sbtile[o_l * 9 + ii] =
            __ldg(scale_base + (oBase + o_l) * IN_DIM + i0 + ii);
    }
    __syncthreads();

    int b0 = bg * 8;              // this warp's batch offset (uniform)
    const float* sbase = stile + b0;

    u64 acc[4][4];
#pragma unroll
    for (int j = 0; j < 4; j++)
#pragma unroll
        for (int p = 0; p < 4; p++) acc[j][p] = 0ULL;

#pragma unroll 2
    for (int ii = 0; ii < CHUNK; ii++) {
        const float* srow = sbase + ii * (NROWS * BATCH);

        // two k-halves to cap register pressure
#pragma unroll
        for (int half = 0; half < 2; half++) {
            float4 w4[4];
#pragma unroll
            for (int j = 0; j < 4; j++)
                w4[j] = *reinterpret_cast<const float4*>(
                    wtile + (j * 32 + lane) * WSTRIDE + ii * 8 + half * 4);

#pragma unroll
            for (int kk = 0; kk < 4; kk++) {
                int k = half * 4 + kk;
                const double2* s2p = reinterpret_cast<const double2*>(srow + k * BATCH);
                double2 sa = s2p[0], sb = s2p[1];       // warp-uniform -> broadcast
                u64 s[4] = {__double_as_longlong(sa.x), __double_as_longlong(sa.y),
                            __double_as_longlong(sb.x), __double_as_longlong(sb.y)};
#pragma unroll
                for (int j = 0; j < 4; j++) {
                    float wv = (kk == 0) ? w4[j].x : (kk == 1) ? w4[j].y
                             : (kk == 2) ? w4[j].z : w4[j].w;
                    u64 wk = pk2(wv);
#pragma unroll
                    for (int p = 0; p < 4; p++) fma2(acc[j][p], wk, s[p]);
                }
            }
        }
        // silu row (k = 8) with scale_base weights
        {
            const double2* s2p = reinterpret_cast<const double2*>(srow + NUMF * BATCH);
            double2 sa = s2p[0], sb = s2p[1];
            u64 s[4] = {__double_as_longlong(sa.x), __double_as_longlong(sa.y),
                        __double_as_longlong(sb.x), __double_as_longlong(sb.y)};
#pragma unroll
            for (int j = 0; j < 4; j++) {
                u64 wb = pk2(sbtile[(j * 32 + lane) * 9 + ii]);
#pragma unroll
                for (int p = 0; p < 4; p++) fma2(acc[j][p], wb, s[p]);
            }
        }
    }

    // ---- epilogue: lane-coalesced u64 stores into [split][bp][o] ----
#pragma unroll
    for (int j = 0; j < 4; j++) {
        int o = oBase + j * 32 + lane;
#pragma unroll
        for (int p = 0; p < 4; p++) {
            g_part[((size_t)(split * 16 + bg * 4 + p)) * OUT_DIM + o] = acc[j][p];
        }
    }
}

// -------- Kernel R: reduce 96 splits + bias (MLP-16) --------
__global__ __launch_bounds__(128) void reduce_kernel(const float* __restrict__ bias_w,
                                                     float* __restrict__ y) {
    int t = blockIdx.x * blockDim.x + threadIdx.x;
    if (t >= OUT_DIM * (BATCH / 2)) return;
    int o = t % OUT_DIM;          // lane-consecutive o -> coalesced
    int bp = t / OUT_DIM;

    const u64* p = g_part + (size_t)bp * OUT_DIM + o;
    const size_t stride = (size_t)16 * OUT_DIM;

    u64 a[16];
#pragma unroll
    for (int q = 0; q < 16; q++) a[q] = p[(size_t)q * stride];
#pragma unroll
    for (int r = 1; r < NSPLIT / 16; r++)
#pragma unroll
        for (int q = 0; q < 16; q++)
            add2(a[q], p[(size_t)(r * 16 + q) * stride]);
#pragma unroll
    for (int q = 8; q > 0; q >>= 1)
#pragma unroll
        for (int m = 0; m < q; m++) add2(a[m], a[m + q]);

    float lo, hi;
    upk2(a[0], lo, hi);
    float bw = __ldg(bias_w + o);
    y[(2 * bp) * OUT_DIM + o] = lo + bw;
    y[(2 * bp + 1) * OUT_DIM + o] = hi + bw;
}

extern "C" void kernel_launch(void* const* d_in, const int* in_sizes, int n_in,
                              void* d_out, int out_size) {
    // metadata order: x, grid, coef, bias_w, scale_base, scale_sp
    const float* x          = (const float*)d_in[0];
    const float* grid       = (const float*)d_in[1];
    const float* coef       = (const float*)d_in[2];
    const float* bias_w     = (const float*)d_in[3];
    const float* scale_base = (const float*)d_in[4];
    const float* scale_sp   = (const float*)d_in[5];
    float* y = (float*)d_out;

    precompute_kernel<<<IN_DIM / 4, 128>>>(x, grid);
    dim3 g(OUT_DIM / O_TILE, NSPLIT);   // 6 x 96 = 576 blocks, ~one full wave at 4/SM
    gemm_kernel<<<g, THREADS>>>(coef, scale_sp, scale_base);
    reduce_kernel<<<(OUT_DIM * (BATCH / 2)) / 128, 128>>>(bias_w, y);
}

// round 9
// speedup vs baseline: 1.0014x; 1.0014x over previous
#include <cuda_runtime.h>

#define IN_DIM 768
#define OUT_DIM 768
#define BATCH 32
#define NUMF 8
#define NROWS 9                    // 8 sin rows + 1 silu row

#define CHUNK 8                    // i's per block
#define NSPLIT (IN_DIM / CHUNK)    // 96 k-splits
#define O_TILE 128
#define THREADS 256                // 8 warps: bg = warp&3, j-half = warp>>2
#define WSTRIDE 68                 // floats/row; 68%32==4 -> lanes tile all banks

typedef unsigned long long u64;

// Partials, layout [split][bpair(16)][o(768)] packed f32x2 -> coalesced stores & reduce
__device__ u64 g_part[NSPLIT * (BATCH / 2) * OUT_DIM];

// ---- f32x2 helpers ----
__device__ __forceinline__ u64 pk2(float v) {
    u64 r; asm("mov.b64 %0, {%1, %1};" : "=l"(r) : "f"(v)); return r;
}
__device__ __forceinline__ u64 pk2ab(float a, float b) {
    u64 r; asm("mov.b64 %0, {%1, %2};" : "=l"(r) : "f"(a), "f"(b)); return r;
}
__device__ __forceinline__ void upk2(u64 v, float& lo, float& hi) {
    asm("mov.b64 {%0, %1}, %2;" : "=f"(lo), "=f"(hi) : "l"(v));
}
__device__ __forceinline__ void fma2(u64& d, u64 a, u64 b) {
    asm("fma.rn.f32x2 %0, %1, %2, %0;" : "+l"(d) : "l"(a), "l"(b));
}
__device__ __forceinline__ u64 mul2(u64 a, u64 b) {
    u64 r; asm("mul.rn.f32x2 %0, %1, %2;" : "=l"(r) : "l"(a), "l"(b)); return r;
}
__device__ __forceinline__ void add2(u64& d, u64 a) {
    asm("add.rn.f32x2 %0, %0, %1;" : "+l"(d) : "l"(a));
}

// -------- Kernel G: fused basis + skinny GEMM --------
// Warp w: bg = w&3 (batch-group of 8), jh = w>>2 (o-half). Lane = o.
// Thread tile: 2 o x 8 b. s-row loads warp-uniform -> smem broadcast.
__global__ __launch_bounds__(THREADS, 4) void gemm_kernel(
    const float* __restrict__ x,
    const float* __restrict__ grid,
    const float* __restrict__ coef,
    const float* __restrict__ scale_sp,
    const float* __restrict__ scale_base) {

    __shared__ __align__(16) float stile[CHUNK * NROWS * BATCH];    // 9216 B
    __shared__ __align__(16) float wtile[O_TILE * WSTRIDE];         // 34816 B
    __shared__ float sbtile[O_TILE * 9];                            // 4608 B (stride 9)

    int tid = threadIdx.x;
    int lane = tid & 31;
    int warp = tid >> 5;
    int split = blockIdx.y;
    int i0 = split * CHUNK;
    int oBase = blockIdx.x * O_TILE;

    // ---- fused basis: each thread computes one (ii, b) column ----
    {
        int ii = tid >> 5;        // 0..7
        int b = tid & 31;
        float xv = x[b * IN_DIM + i0 + ii];
        float* col = stile + ii * (NROWS * BATCH) + b;

        float theta = __ldg(grid) * xv;
        float s1 = __sinf(theta);
        float c2 = 2.0f * __cosf(theta);
        float sm1 = s1, sm2 = 0.0f;
        col[0] = s1;
#pragma unroll
        for (int k = 1; k < NUMF; k++) {
            float sk = fmaf(c2, sm1, -sm2);
            sm2 = sm1; sm1 = sk;
            col[k * BATCH] = sk;
        }
        col[NUMF * BATCH] = xv / (1.0f + __expf(-xv));   // silu
    }

    // ---- stage w pre-scaled by scale_sp (packed f32x2 folds) ----
#pragma unroll
    for (int f = tid; f < O_TILE * CHUNK; f += THREADS) {   // 1024 granules, 4/thread
        int o_l = f >> 3;
        int i_l = f & 7;
        int idx = (oBase + o_l) * IN_DIM + i0 + i_l;
        float4 c0 = reinterpret_cast<const float4*>(coef)[idx * 2];
        float4 c1 = reinterpret_cast<const float4*>(coef)[idx * 2 + 1];
        u64 sp2 = pk2(__ldg(scale_sp + idx));
        u64 v0 = mul2(pk2ab(c0.x, c0.y), sp2);
        u64 v1 = mul2(pk2ab(c0.z, c0.w), sp2);
        u64 v2 = mul2(pk2ab(c1.x, c1.y), sp2);
        u64 v3 = mul2(pk2ab(c1.z, c1.w), sp2);
        u64* wp = reinterpret_cast<u64*>(wtile + o_l * WSTRIDE + i_l * 8);
        wp[0] = v0; wp[1] = v1; wp[2] = v2; wp[3] = v3;
    }
#pragma unroll
    for (int f = tid; f < O_TILE * CHUNK; f += THREADS) {
        int o_l = f >> 3;
        int ii = f & 7;
        sbtile[o_l * 9 + ii] =
            __ldg(scale_base + (oBase + o_l) * IN_DIM + i0 + ii);
    }
    __syncthreads();

    int bg = warp & 3;
    int jh = warp >> 2;           // o-half: rows (jh*2+j)*32+lane
    int b0 = bg * 8;
    const float* sbase = stile + b0;

    u64 acc[2][4];
#pragma unroll
    for (int j = 0; j < 2; j++)
#pragma unroll
        for (int p = 0; p < 4; p++) acc[j][p] = 0ULL;

#pragma unroll 2
    for (int ii = 0; ii < CHUNK; ii++) {
        const float* srow = sbase + ii * (NROWS * BATCH);

#pragma unroll
        for (int half = 0; half < 2; half++) {
            float4 w4[2];
#pragma unroll
            for (int j = 0; j < 2; j++)
                w4[j] = *reinterpret_cast<const float4*>(
                    wtile + ((jh * 2 + j) * 32 + lane) * WSTRIDE + ii * 8 + half * 4);

#pragma unroll
            for (int kk = 0; kk < 4; kk++) {
                int k = half * 4 + kk;
                const double2* s2p = reinterpret_cast<const double2*>(srow + k * BATCH);
                double2 sa = s2p[0], sb = s2p[1];       // warp-uniform -> broadcast
                u64 s[4] = {__double_as_longlong(sa.x), __double_as_longlong(sa.y),
                            __double_as_longlong(sb.x), __double_as_longlong(sb.y)};
#pragma unroll
                for (int j = 0; j < 2; j++) {
                    float wv = (kk == 0) ? w4[j].x : (kk == 1) ? w4[j].y
                             : (kk == 2) ? w4[j].z : w4[j].w;
                    u64 wk = pk2(wv);
#pragma unroll
                    for (int p = 0; p < 4; p++) fma2(acc[j][p], wk, s[p]);
                }
            }
        }
        // silu row with scale_base weights
        {
            const double2* s2p = reinterpret_cast<const double2*>(srow + NUMF * BATCH);
            double2 sa = s2p[0], sb = s2p[1];
            u64 s[4] = {__double_as_longlong(sa.x), __double_as_longlong(sa.y),
                        __double_as_longlong(sb.x), __double_as_longlong(sb.y)};
#pragma unroll
            for (int j = 0; j < 2; j++) {
                u64 wb = pk2(sbtile[((jh * 2 + j) * 32 + lane) * 9 + ii]);
#pragma unroll
                for (int p = 0; p < 4; p++) fma2(acc[j][p], wb, s[p]);
            }
        }
    }

    // ---- epilogue: lane-coalesced u64 stores into [split][bp][o] ----
#pragma unroll
    for (int j = 0; j < 2; j++) {
        int o = oBase + (jh * 2 + j) * 32 + lane;
#pragma unroll
        for (int p = 0; p < 4; p++) {
            g_part[((size_t)(split * 16 + bg * 4 + p)) * OUT_DIM + o] = acc[j][p];
        }
    }
}

// -------- Kernel R: reduce 96 splits + bias (MLP-16) --------
__global__ __launch_bounds__(128) void reduce_kernel(const float* __restrict__ bias_w,
                                                     float* __restrict__ y) {
    int t = blockIdx.x * blockDim.x + threadIdx.x;
    if (t >= OUT_DIM * (BATCH / 2)) return;
    int o = t % OUT_DIM;          // lane-consecutive o -> coalesced
    int bp = t / OUT_DIM;

    const u64* p = g_part + (size_t)bp * OUT_DIM + o;
    const size_t stride = (size_t)16 * OUT_DIM;

    u64 a[16];
#pragma unroll
    for (int q = 0; q < 16; q++) a[q] = p[(size_t)q * stride];
#pragma unroll
    for (int r = 1; r < NSPLIT / 16; r++)
#pragma unroll
        for (int q = 0; q < 16; q++)
            add2(a[q], p[(size_t)(r * 16 + q) * stride]);
#pragma unroll
    for (int q = 8; q > 0; q >>= 1)
#pragma unroll
        for (int m = 0; m < q; m++) add2(a[m], a[m + q]);

    float lo, hi;
    upk2(a[0], lo, hi);
    float bw = __ldg(bias_w + o);
    y[(2 * bp) * OUT_DIM + o] = lo + bw;
    y[(2 * bp + 1) * OUT_DIM + o] = hi + bw;
}

extern "C" void kernel_launch(void* const* d_in, const int* in_sizes, int n_in,
                              void* d_out, int out_size) {
    // metadata order: x, grid, coef, bias_w, scale_base, scale_sp
    const float* x          = (const float*)d_in[0];
    const float* grid       = (const float*)d_in[1];
    const float* coef       = (const float*)d_in[2];
    const float* bias_w     = (const float*)d_in[3];
    const float* scale_base = (const float*)d_in[4];
    const float* scale_sp   = (const float*)d_in[5];
    float* y = (float*)d_out;

    dim3 g(OUT_DIM / O_TILE, NSPLIT);   // 6 x 96 = 576 blocks, ~one wave at 4/SM
    gemm_kernel<<<g, THREADS>>>(x, grid, coef, scale_sp, scale_base);
    reduce_kernel<<<(OUT_DIM * (BATCH / 2)) / 128, 128>>>(bias_w, y);
}

// round 10
// speedup vs baseline: 1.2037x; 1.2020x over previous
#include <cuda_runtime.h>

#define IN_DIM 768
#define OUT_DIM 768
#define BATCH 32
#define NUMF 8
#define NROWS 9                    // 8 sin rows + 1 silu row

#define CHUNK 8                    // i's per block
#define NSPLIT (IN_DIM / CHUNK)    // 96 k-splits
#define O_TILE 128
#define THREADS 256                // 8 warps: bg = warp&3, j-half = warp>>2
#define WSTRIDE 68                 // floats/row; 68%32==4 -> lanes tile all banks

typedef unsigned long long u64;

// Partials, layout [split][bpair(16)][o(768)] packed f32x2 -> coalesced stores & reduce
__device__ u64 g_part[NSPLIT * (BATCH / 2) * OUT_DIM];

// ---- f32x2 helpers ----
__device__ __forceinline__ u64 pk2(float v) {
    u64 r; asm("mov.b64 %0, {%1, %1};" : "=l"(r) : "f"(v)); return r;
}
__device__ __forceinline__ u64 pk2ab(float a, float b) {
    u64 r; asm("mov.b64 %0, {%1, %2};" : "=l"(r) : "f"(a), "f"(b)); return r;
}
__device__ __forceinline__ void fma2(u64& d, u64 a, u64 b) {
    asm("fma.rn.f32x2 %0, %1, %2, %0;" : "+l"(d) : "l"(a), "l"(b));
}
__device__ __forceinline__ u64 mul2(u64 a, u64 b) {
    u64 r; asm("mul.rn.f32x2 %0, %1, %2;" : "=l"(r) : "l"(a), "l"(b)); return r;
}

// -------- Kernel G: fused basis + skinny GEMM --------
// Warp w: bg = w&3 (batch-group of 8), jh = w>>2 (o-half). Lane = o.
// Thread tile: 2 o x 8 b. s-row loads warp-uniform -> smem broadcast.
__global__ __launch_bounds__(THREADS, 4) void gemm_kernel(
    const float* __restrict__ x,
    const float* __restrict__ grid,
    const float* __restrict__ coef,
    const float* __restrict__ scale_sp,
    const float* __restrict__ scale_base) {

    __shared__ __align__(16) float stile[CHUNK * NROWS * BATCH];    // 9216 B
    __shared__ __align__(16) float wtile[O_TILE * WSTRIDE];         // 34816 B
    __shared__ float sbtile[O_TILE * 9];                            // 4608 B (stride 9)

    int tid = threadIdx.x;
    int lane = tid & 31;
    int warp = tid >> 5;
    int split = blockIdx.y;
    int i0 = split * CHUNK;
    int oBase = blockIdx.x * O_TILE;

    // ---- fused basis: each thread computes one (ii, b) column ----
    {
        int ii = tid >> 5;        // 0..7
        int b = tid & 31;
        float xv = x[b * IN_DIM + i0 + ii];
        float* col = stile + ii * (NROWS * BATCH) + b;

        float theta = __ldg(grid) * xv;
        float s1 = __sinf(theta);
        float c2 = 2.0f * __cosf(theta);
        float sm1 = s1, sm2 = 0.0f;
        col[0] = s1;
#pragma unroll
        for (int k = 1; k < NUMF; k++) {
            float sk = fmaf(c2, sm1, -sm2);
            sm2 = sm1; sm1 = sk;
            col[k * BATCH] = sk;
        }
        col[NUMF * BATCH] = xv / (1.0f + __expf(-xv));   // silu
    }

    // ---- stage w pre-scaled by scale_sp (packed f32x2 folds) ----
#pragma unroll
    for (int f = tid; f < O_TILE * CHUNK; f += THREADS) {   // 1024 granules, 4/thread
        int o_l = f >> 3;
        int i_l = f & 7;
        int idx = (oBase + o_l) * IN_DIM + i0 + i_l;
        float4 c0 = reinterpret_cast<const float4*>(coef)[idx * 2];
        float4 c1 = reinterpret_cast<const float4*>(coef)[idx * 2 + 1];
        u64 sp2 = pk2(__ldg(scale_sp + idx));
        u64 v0 = mul2(pk2ab(c0.x, c0.y), sp2);
        u64 v1 = mul2(pk2ab(c0.z, c0.w), sp2);
        u64 v2 = mul2(pk2ab(c1.x, c1.y), sp2);
        u64 v3 = mul2(pk2ab(c1.z, c1.w), sp2);
        u64* wp = reinterpret_cast<u64*>(wtile + o_l * WSTRIDE + i_l * 8);
        wp[0] = v0; wp[1] = v1; wp[2] = v2; wp[3] = v3;
    }
#pragma unroll
    for (int f = tid; f < O_TILE * CHUNK; f += THREADS) {
        int o_l = f >> 3;
        int ii = f & 7;
        sbtile[o_l * 9 + ii] =
            __ldg(scale_base + (oBase + o_l) * IN_DIM + i0 + ii);
    }
    __syncthreads();

    int bg = warp & 3;
    int jh = warp >> 2;           // o-half: rows (jh*2+j)*32+lane
    int b0 = bg * 8;
    const float* sbase = stile + b0;

    u64 acc[2][4];
#pragma unroll
    for (int j = 0; j < 2; j++)
#pragma unroll
        for (int p = 0; p < 4; p++) acc[j][p] = 0ULL;

#pragma unroll 2
    for (int ii = 0; ii < CHUNK; ii++) {
        const float* srow = sbase + ii * (NROWS * BATCH);

#pragma unroll
        for (int half = 0; half < 2; half++) {
            float4 w4[2];
#pragma unroll
            for (int j = 0; j < 2; j++)
                w4[j] = *reinterpret_cast<const float4*>(
                    wtile + ((jh * 2 + j) * 32 + lane) * WSTRIDE + ii * 8 + half * 4);

#pragma unroll
            for (int kk = 0; kk < 4; kk++) {
                int k = half * 4 + kk;
                const double2* s2p = reinterpret_cast<const double2*>(srow + k * BATCH);
                double2 sa = s2p[0], sb = s2p[1];       // warp-uniform -> broadcast
                u64 s[4] = {__double_as_longlong(sa.x), __double_as_longlong(sa.y),
                            __double_as_longlong(sb.x), __double_as_longlong(sb.y)};
#pragma unroll
                for (int j = 0; j < 2; j++) {
                    float wv = (kk == 0) ? w4[j].x : (kk == 1) ? w4[j].y
                             : (kk == 2) ? w4[j].z : w4[j].w;
                    u64 wk = pk2(wv);
#pragma unroll
                    for (int p = 0; p < 4; p++) fma2(acc[j][p], wk, s[p]);
                }
            }
        }
        // silu row with scale_base weights
        {
            const double2* s2p = reinterpret_cast<const double2*>(srow + NUMF * BATCH);
            double2 sa = s2p[0], sb = s2p[1];
            u64 s[4] = {__double_as_longlong(sa.x), __double_as_longlong(sa.y),
                        __double_as_longlong(sb.x), __double_as_longlong(sb.y)};
#pragma unroll
            for (int j = 0; j < 2; j++) {
                u64 wb = pk2(sbtile[((jh * 2 + j) * 32 + lane) * 9 + ii]);
#pragma unroll
                for (int p = 0; p < 4; p++) fma2(acc[j][p], wb, s[p]);
            }
        }
    }

    // ---- epilogue: lane-coalesced u64 stores into [split][bp][o] ----
#pragma unroll
    for (int j = 0; j < 2; j++) {
        int o = oBase + (jh * 2 + j) * 32 + lane;
#pragma unroll
        for (int p = 0; p < 4; p++) {
            g_part[((size_t)(split * 16 + bg * 4 + p)) * OUT_DIM + o] = acc[j][p];
        }
    }
}

// -------- Kernel R: parallel reduce over 96 splits + bias --------
// 384 blocks x 256 thr. Block = (o-group of 32, bp); warp w reduces splits
// [w*12, w*12+12); cross-warp combine in smem; warp 0 writes y.
__global__ __launch_bounds__(256) void reduce_kernel(const float* __restrict__ bias_w,
                                                     float* __restrict__ y) {
    __shared__ float2 sm[8][32];

    int og = blockIdx.x >> 4;          // 0..23
    int bp = blockIdx.x & 15;
    int w = threadIdx.x >> 5;
    int lane = threadIdx.x & 31;
    int o = og * 32 + lane;

    const float2* p = reinterpret_cast<const float2*>(g_part)
                    + (size_t)bp * OUT_DIM + o;
    const size_t sstride = (size_t)16 * OUT_DIM;   // split stride in float2

    // MLP-12 batched loads, then sum
    float2 v[12];
#pragma unroll
    for (int r = 0; r < 12; r++)
        v[r] = p[(size_t)(w * 12 + r) * sstride];

    float2 acc = v[0];
#pragma unroll
    for (int r = 1; r < 12; r++) { acc.x += v[r].x; acc.y += v[r].y; }

    sm[w][lane] = acc;
    __syncthreads();

    if (w == 0) {
        float2 t = sm[0][lane];
#pragma unroll
        for (int q = 1; q < 8; q++) { t.x += sm[q][lane].x; t.y += sm[q][lane].y; }
        float bw = __ldg(bias_w + o);
        y[(2 * bp) * OUT_DIM + o] = t.x + bw;
        y[(2 * bp + 1) * OUT_DIM + o] = t.y + bw;
    }
}

extern "C" void kernel_launch(void* const* d_in, const int* in_sizes, int n_in,
                              void* d_out, int out_size) {
    // metadata order: x, grid, coef, bias_w, scale_base, scale_sp
    const float* x          = (const float*)d_in[0];
    const float* grid       = (const float*)d_in[1];
    const float* coef       = (const float*)d_in[2];
    const float* bias_w     = (const float*)d_in[3];
    const float* scale_base = (const float*)d_in[4];
    const float* scale_sp   = (const float*)d_in[5];
    float* y = (float*)d_out;

    dim3 g(OUT_DIM / O_TILE, NSPLIT);   // 6 x 96 = 576 blocks, ~one wave at 4/SM
    gemm_kernel<<<g, THREADS>>>(x, grid, coef, scale_sp, scale_base);
    reduce_kernel<<<(OUT_DIM / 32) * (BATCH / 2), 256>>>(bias_w, y);  // 384 blocks
}